// round 9
// baseline (speedup 1.0000x reference)
#include <cuda_runtime.h>
#include <cstdint>

#define BDIM 64
#define TDIM 2048
#define DDIM 256
#define HDIM 256
#define G3   768

__device__ float g_xg[(size_t)BDIM * TDIM * G3];

// ---------------- f32x2 helpers ----------------
__device__ __forceinline__ unsigned long long pk2(float x, float y) {
    unsigned long long r;
    asm("mov.b64 %0, {%1, %2};" : "=l"(r) : "f"(x), "f"(y));
    return r;
}
__device__ __forceinline__ void upk2(unsigned long long p, float& x, float& y) {
    asm("mov.b64 {%0, %1}, %2;" : "=f"(x), "=f"(y) : "l"(p));
}
__device__ __forceinline__ unsigned long long fma2(unsigned long long a,
                                                   unsigned long long b,
                                                   unsigned long long c) {
    unsigned long long d;
    asm("fma.rn.f32x2 %0, %1, %2, %3;" : "=l"(d) : "l"(a), "l"(b), "l"(c));
    return d;
}

// ---------------- Kernel 1: projection GEMM (unchanged, known-good) ----------------
#define BM 64
#define BN 64
#define BK 32

__global__ __launch_bounds__(256) void proj_gemm(const float* __restrict__ x,
                                                 const float* __restrict__ W,
                                                 const float* __restrict__ bias) {
    __shared__ float As[BK][BM + 4];
    __shared__ float Bs[BK][BN + 4];
    const int tid = threadIdx.x;
    const int gm = blockIdx.x * BM;
    const int gn = blockIdx.y * BN;
    const int m4 = (tid >> 4) * 4;
    const int n4 = (tid & 15) * 4;

    unsigned long long acc[4][2];
#pragma unroll
    for (int i = 0; i < 4; i++) { acc[i][0] = 0ull; acc[i][1] = 0ull; }

    for (int kt = 0; kt < DDIM; kt += BK) {
#pragma unroll
        for (int j = 0; j < 2; j++) {
            int idx = tid + j * 256;
            int row = idx >> 3;
            int c4  = (idx & 7) * 4;
            float4 va = *(const float4*)&x[(size_t)(gm + row) * DDIM + kt + c4];
            As[c4 + 0][row] = va.x; As[c4 + 1][row] = va.y;
            As[c4 + 2][row] = va.z; As[c4 + 3][row] = va.w;
            float4 vb = *(const float4*)&W[(size_t)(gn + row) * DDIM + kt + c4];
            Bs[c4 + 0][row] = vb.x; Bs[c4 + 1][row] = vb.y;
            Bs[c4 + 2][row] = vb.z; Bs[c4 + 3][row] = vb.w;
        }
        __syncthreads();
#pragma unroll
        for (int k = 0; k < BK; k++) {
            float4 av = *(const float4*)&As[k][m4];
            float4 bv = *(const float4*)&Bs[k][n4];
            unsigned long long bp0 = pk2(bv.x, bv.y);
            unsigned long long bp1 = pk2(bv.z, bv.w);
            unsigned long long aa;
            aa = pk2(av.x, av.x);
            acc[0][0] = fma2(aa, bp0, acc[0][0]); acc[0][1] = fma2(aa, bp1, acc[0][1]);
            aa = pk2(av.y, av.y);
            acc[1][0] = fma2(aa, bp0, acc[1][0]); acc[1][1] = fma2(aa, bp1, acc[1][1]);
            aa = pk2(av.z, av.z);
            acc[2][0] = fma2(aa, bp0, acc[2][0]); acc[2][1] = fma2(aa, bp1, acc[2][1]);
            aa = pk2(av.w, av.w);
            acc[3][0] = fma2(aa, bp0, acc[3][0]); acc[3][1] = fma2(aa, bp1, acc[3][1]);
        }
        __syncthreads();
    }

    float4 bb = *(const float4*)&bias[gn + n4];
#pragma unroll
    for (int mi = 0; mi < 4; mi++) {
        float o0, o1, o2, o3;
        upk2(acc[mi][0], o0, o1);
        upk2(acc[mi][1], o2, o3);
        float4 o = make_float4(o0 + bb.x, o1 + bb.y, o2 + bb.z, o3 + bb.w);
        *(float4*)&g_xg[(size_t)(gm + m4 + mi) * G3 + gn + n4] = o;
    }
}

// ---------------- Kernel 2: CLSZ=4, register W, batch-pipelined seq-flag sync ----------------
#define CLSZ 4
#define RTH  384
#define IDXC 64
#define NROW 192

__device__ __forceinline__ float sigm_f(float x) { return 1.f / (1.f + __expf(-x)); }
__device__ __forceinline__ float tanh_f(float x) { return 1.f - 2.f / (__expf(2.f * x) + 1.f); }

__device__ __forceinline__ void st_dsmem_u64(uint32_t saddr, uint32_t rk, unsigned long long v) {
    uint32_t ra;
    asm volatile("mapa.shared::cluster.u32 %0, %1, %2;" : "=r"(ra) : "r"(saddr), "r"(rk));
    asm volatile("st.shared::cluster.u64 [%0], %1;" :: "r"(ra), "l"(v) : "memory");
}
__device__ __forceinline__ void post_flag(uint32_t laddr, uint32_t rk, int val) {
    uint32_t ra;
    asm volatile("mapa.shared::cluster.u32 %0, %1, %2;" : "=r"(ra) : "r"(laddr), "r"(rk));
    asm volatile("st.release.cluster.shared::cluster.u32 [%0], %1;" :: "r"(ra), "r"(val) : "memory");
}
__device__ __forceinline__ void cluster_arrive() {
    asm volatile("barrier.cluster.arrive.aligned;" ::: "memory");
}
__device__ __forceinline__ void cluster_wait() {
    asm volatile("barrier.cluster.wait.aligned;" ::: "memory");
}

__global__ __launch_bounds__(RTH, 1) void gru_rec(const float* __restrict__ h0,
                                                  const float* __restrict__ W_hh,
                                                  const float* __restrict__ b_hh,
                                                  float* __restrict__ hs,
                                                  float* __restrict__ hT) {
    __shared__ alignas(16) float sh_h[2][2][HDIM];   // [batch][buf][k]
    __shared__ alignas(16) float sh_red[2][RTH];     // [batch][tid]
    __shared__ alignas(16) int   sh_flag[2][2][CLSZ];// [batch][buf][src rank]

    uint32_t rank; asm("mov.u32 %0, %%cluster_ctarank;" : "=r"(rank));
    const int tid = threadIdx.x;
    const int cb = (blockIdx.x >> 2) * 2;

    const int kh = tid >= NROW;            // k-half
    const int r  = tid - kh * NROW;        // row 0..191
    const int g  = r >> 6, il = r & 63;
    const int grow = g * HDIM + (int)rank * IDXC + il;

    // ---- W half-row -> 64 packed f32x2 regs; wq[m] covers k = kh*128 + 2m
    unsigned long long wq[64];
    {
        const ulonglong2* wp = (const ulonglong2*)(W_hh + (size_t)grow * HDIM + kh * 128);
#pragma unroll
        for (int j = 0; j < 32; j++) { ulonglong2 u = wp[j]; wq[2*j] = u.x; wq[2*j+1] = u.y; }
    }
    // ---- gate-thread biases (tid<64: index il = tid)
    float bhr = 0.f, bhz = 0.f, bhn = 0.f;
    if (tid < IDXC) {
        int gi = (int)rank * IDXC + tid;
        bhr = b_hh[gi]; bhz = b_hh[HDIM + gi]; bhn = b_hh[2 * HDIM + gi];
    }
    // ---- h0 -> buf 0 for both batches; init flags
    for (int i = tid; i < 2 * HDIM; i += RTH) {
        int X = i >> 8, k = i & 255;
        sh_h[X][0][k] = h0[(size_t)(cb + X) * HDIM + k];
    }
    if (tid < 16) {
        int X = tid >> 3, bf = (tid >> 2) & 1, s = tid & 3;
        sh_flag[X][bf][s] = bf ? -1 : 0;   // buf0 holds h(0): ready at t=0
    }
    __syncthreads();
    cluster_arrive();
    cluster_wait();

    const uint32_t h_s    = (uint32_t)__cvta_generic_to_shared(sh_h);
    const uint32_t flag_s = (uint32_t)__cvta_generic_to_shared(sh_flag);

    auto phase = [&](int X, int t) {
        const int buf = t & 1;
        // xg prefetch (gate threads) before polling — DRAM latency hidden
        float xr = 0.f, xz = 0.f, xn = 0.f;
        if (tid < IDXC) {
            const float* xp = g_xg + ((size_t)(cb + X) * TDIM + t) * G3
                            + (size_t)rank * IDXC + tid;
            xr = xp[0]; xz = xp[256]; xn = xp[512];
        }
        // poll the 4 source flags for this batch/buffer (acquire)
        {
            uint32_t fa = flag_s + 4u * (uint32_t)((X * 2 + buf) * CLSZ);
            int ok;
            do {
                int v0, v1, v2, v3;
                asm volatile("ld.acquire.cluster.shared::cta.u32 %0, [%1];" : "=r"(v0) : "r"(fa));
                asm volatile("ld.acquire.cluster.shared::cta.u32 %0, [%1];" : "=r"(v1) : "r"(fa + 4));
                asm volatile("ld.acquire.cluster.shared::cta.u32 %0, [%1];" : "=r"(v2) : "r"(fa + 8));
                asm volatile("ld.acquire.cluster.shared::cta.u32 %0, [%1];" : "=r"(v3) : "r"(fa + 12));
                ok = (v0 >= t) && (v1 >= t) && (v2 >= t) && (v3 >= t);
            } while (!ok);
        }
        const float* hb = sh_h[X][buf];
        // half-row matvec: 4 chains over 32 ulonglong2 h entries
        const ulonglong2* hp = (const ulonglong2*)(hb + kh * 128);
        unsigned long long a0 = 0ull, a1 = 0ull, a2 = 0ull, a3 = 0ull;
#pragma unroll
        for (int c = 0; c < 8; c++) {
            ulonglong2 v0 = hp[c];
            a0 = fma2(wq[2*c+0],    v0.x, a0); a0 = fma2(wq[2*c+1],    v0.y, a0);
            ulonglong2 v1 = hp[8 + c];
            a1 = fma2(wq[16+2*c+0], v1.x, a1); a1 = fma2(wq[16+2*c+1], v1.y, a1);
            ulonglong2 v2 = hp[16 + c];
            a2 = fma2(wq[32+2*c+0], v2.x, a2); a2 = fma2(wq[32+2*c+1], v2.y, a2);
            ulonglong2 v3 = hp[24 + c];
            a3 = fma2(wq[48+2*c+0], v3.x, a3); a3 = fma2(wq[48+2*c+1], v3.y, a3);
        }
        unsigned long long sA = fma2(pk2(1.f, 1.f), a0, a1);
        unsigned long long sB = fma2(pk2(1.f, 1.f), a2, a3);
        unsigned long long sC = fma2(pk2(1.f, 1.f), sA, sB);
        float xl, xh2;
        upk2(sC, xl, xh2);
        sh_red[X][tid] = xl + xh2;
        __syncthreads();

        if (tid < IDXC) {
            const int gi = (int)rank * IDXC + tid;
            float hr  = sh_red[X][tid]        + sh_red[X][NROW + tid];
            float hz  = sh_red[X][64 + tid]   + sh_red[X][NROW + 64 + tid];
            float hnv = sh_red[X][128 + tid]  + sh_red[X][NROW + 128 + tid];
            float hprev = hb[gi];
            float rg = sigm_f(xr + hr + bhr);
            float zg = sigm_f(xz + hz + bhz);
            float ng = tanh_f(xn + rg * (hnv + bhn));
            float hnew = (1.f - zg) * ng + zg * hprev;

            float hpart = __shfl_down_sync(0xffffffffu, hnew, 1);
            if (t < TDIM - 1) {
                if ((tid & 1) == 0) {
                    unsigned long long pv = pk2(hnew, hpart);
                    uint32_t laddr = h_s + 4u * (uint32_t)((X * 2 + (buf ^ 1)) * HDIM + gi);
#pragma unroll
                    for (uint32_t dr = 0; dr < CLSZ; dr++) st_dsmem_u64(laddr, dr, pv);
                }
                // gate-group barrier, then one thread releases + posts seq flags
                asm volatile("bar.sync %0, 64;" :: "r"(2 + X) : "memory");
                if (tid == 0) {
                    asm volatile("fence.acq_rel.cluster;" ::: "memory");
                    uint32_t fl = flag_s + 4u * (uint32_t)((X * 2 + (buf ^ 1)) * CLSZ + (int)rank);
#pragma unroll
                    for (uint32_t dr = 0; dr < CLSZ; dr++) post_flag(fl, dr, t + 1);
                }
            }
            if ((tid & 1) == 0)
                *(float2*)&hs[((size_t)(cb + X) * TDIM + t) * HDIM + gi] = make_float2(hnew, hpart);
            if (t == TDIM - 1) hT[(size_t)(cb + X) * HDIM + gi] = hnew;
        }
    };

    for (int t = 0; t < TDIM; t++) {
        phase(0, t);
        phase(1, t);
    }

    cluster_arrive();
    cluster_wait();
}

// ---------------- launch ----------------
extern "C" void kernel_launch(void* const* d_in, const int* in_sizes, int n_in,
                              void* d_out, int out_size) {
    (void)in_sizes; (void)n_in; (void)out_size;
    const float* x    = (const float*)d_in[0];
    const float* h0   = (const float*)d_in[1];
    const float* W_ih = (const float*)d_in[2];
    const float* W_hh = (const float*)d_in[3];
    const float* b_ih = (const float*)d_in[4];
    const float* b_hh = (const float*)d_in[5];
    float* out = (float*)d_out;
    float* hs = out;
    float* hT = out + (size_t)BDIM * TDIM * HDIM;

    dim3 g1((BDIM * TDIM) / BM, G3 / BN);
    proj_gemm<<<g1, 256>>>(x, W_ih, b_ih);

    cudaLaunchConfig_t cfg = {};
    cfg.gridDim = dim3(32 * CLSZ, 1, 1);
    cfg.blockDim = dim3(RTH, 1, 1);
    cfg.dynamicSmemBytes = 0;
    cfg.stream = 0;
    cudaLaunchAttribute attrs[1];
    attrs[0].id = cudaLaunchAttributeClusterDimension;
    attrs[0].val.clusterDim.x = CLSZ;
    attrs[0].val.clusterDim.y = 1;
    attrs[0].val.clusterDim.z = 1;
    cfg.attrs = attrs;
    cfg.numAttrs = 1;
    cudaLaunchKernelEx(&cfg, gru_rec, h0, W_hh, b_hh, hs, hT);
}

// round 10
// speedup vs baseline: 1.8406x; 1.8406x over previous
#include <cuda_runtime.h>
#include <cstdint>

#define BDIM 64
#define TDIM 2048
#define DDIM 256
#define HDIM 256
#define G3   768

__device__ float g_xg[(size_t)BDIM * TDIM * G3];

// ---------------- f32x2 helpers ----------------
__device__ __forceinline__ unsigned long long pk2(float x, float y) {
    unsigned long long r;
    asm("mov.b64 %0, {%1, %2};" : "=l"(r) : "f"(x), "f"(y));
    return r;
}
__device__ __forceinline__ void upk2(unsigned long long p, float& x, float& y) {
    asm("mov.b64 {%0, %1}, %2;" : "=f"(x), "=f"(y) : "l"(p));
}
__device__ __forceinline__ unsigned long long fma2(unsigned long long a,
                                                   unsigned long long b,
                                                   unsigned long long c) {
    unsigned long long d;
    asm("fma.rn.f32x2 %0, %1, %2, %3;" : "=l"(d) : "l"(a), "l"(b), "l"(c));
    return d;
}

// ---------------- Kernel 1: projection GEMM (dup-A smem, reg prefetch) ----------------
#define BM 64
#define BN 64
#define BK 32
#define AST (2 * BM + 8)   // duplicated-A row stride (floats), even for LDS.64 align
#define BST (BN + 8)

__global__ __launch_bounds__(256) void proj_gemm(const float* __restrict__ x,
                                                 const float* __restrict__ W,
                                                 const float* __restrict__ bias) {
    __shared__ float As2[BK][AST];   // A duplicated: [k][2m] == [k][2m+1]
    __shared__ float Bs[BK][BST];    // B: [k][n]
    const int tid = threadIdx.x;
    const int gn = blockIdx.x * BN;  // N fast dim: 12 adjacent blocks share x tile (L2)
    const int gm = blockIdx.y * BM;
    const int m4 = (tid >> 4) * 4;
    const int n4 = (tid & 15) * 4;

    // loader mapping: idx = tid + j*256 in [0,512): row = idx>>3, c4 = (idx&7)*4
    const int r0 = tid >> 3,        c40 = (tid & 7) * 4;
    const int r1 = (tid + 256) >> 3, c41 = c40;   // j=1: row = r0+32

    unsigned long long acc[4][2];
#pragma unroll
    for (int i = 0; i < 4; i++) { acc[i][0] = 0ull; acc[i][1] = 0ull; }

    // prologue: load tile 0
    float4 va0 = *(const float4*)&x[(size_t)(gm + r0) * DDIM + c40];
    float4 va1 = *(const float4*)&x[(size_t)(gm + r1) * DDIM + c41];
    float4 vb0 = *(const float4*)&W[(size_t)(gn + r0) * DDIM + c40];
    float4 vb1 = *(const float4*)&W[(size_t)(gn + r1) * DDIM + c41];
#pragma unroll
    for (int i = 0; i < 4; i++) {
        float v;
        v = (&va0.x)[i]; *(float2*)&As2[c40 + i][2 * r0] = make_float2(v, v);
        v = (&va1.x)[i]; *(float2*)&As2[c41 + i][2 * r1] = make_float2(v, v);
        Bs[c40 + i][r0] = (&vb0.x)[i];
        Bs[c41 + i][r1] = (&vb1.x)[i];
    }
    __syncthreads();

    for (int kt = 0; kt < DDIM / BK; kt++) {
        float4 na0, na1, nb0, nb1;
        if (kt < DDIM / BK - 1) {
            int ko = (kt + 1) * BK;
            na0 = *(const float4*)&x[(size_t)(gm + r0) * DDIM + ko + c40];
            na1 = *(const float4*)&x[(size_t)(gm + r1) * DDIM + ko + c41];
            nb0 = *(const float4*)&W[(size_t)(gn + r0) * DDIM + ko + c40];
            nb1 = *(const float4*)&W[(size_t)(gn + r1) * DDIM + ko + c41];
        }
#pragma unroll
        for (int k = 0; k < BK; k++) {
            ulonglong2 bp = *(const ulonglong2*)&Bs[k][n4];
            unsigned long long aa0 = *(const unsigned long long*)&As2[k][2 * (m4 + 0)];
            unsigned long long aa1 = *(const unsigned long long*)&As2[k][2 * (m4 + 1)];
            unsigned long long aa2 = *(const unsigned long long*)&As2[k][2 * (m4 + 2)];
            unsigned long long aa3 = *(const unsigned long long*)&As2[k][2 * (m4 + 3)];
            acc[0][0] = fma2(aa0, bp.x, acc[0][0]); acc[0][1] = fma2(aa0, bp.y, acc[0][1]);
            acc[1][0] = fma2(aa1, bp.x, acc[1][0]); acc[1][1] = fma2(aa1, bp.y, acc[1][1]);
            acc[2][0] = fma2(aa2, bp.x, acc[2][0]); acc[2][1] = fma2(aa2, bp.y, acc[2][1]);
            acc[3][0] = fma2(aa3, bp.x, acc[3][0]); acc[3][1] = fma2(aa3, bp.y, acc[3][1]);
        }
        __syncthreads();
        if (kt < DDIM / BK - 1) {
#pragma unroll
            for (int i = 0; i < 4; i++) {
                float v;
                v = (&na0.x)[i]; *(float2*)&As2[c40 + i][2 * r0] = make_float2(v, v);
                v = (&na1.x)[i]; *(float2*)&As2[c41 + i][2 * r1] = make_float2(v, v);
                Bs[c40 + i][r0] = (&nb0.x)[i];
                Bs[c41 + i][r1] = (&nb1.x)[i];
            }
            __syncthreads();
        }
    }

    float4 bb = *(const float4*)&bias[gn + n4];
#pragma unroll
    for (int mi = 0; mi < 4; mi++) {
        float o0, o1, o2, o3;
        upk2(acc[mi][0], o0, o1);
        upk2(acc[mi][1], o2, o3);
        float4 o = make_float4(o0 + bb.x, o1 + bb.y, o2 + bb.z, o3 + bb.w);
        *(float4*)&g_xg[(size_t)(gm + m4 + mi) * G3 + gn + n4] = o;
    }
}

// ---------------- Kernel 2: CLSZ=4, register W, cluster barrier (R7, verbatim) ----------------
#define CLSZ 4
#define RTH  384
#define IDXC 64
#define NROW 192

__device__ __forceinline__ float sigm_f(float x) { return 1.f / (1.f + __expf(-x)); }
__device__ __forceinline__ float tanh_f(float x) { return 1.f - 2.f / (__expf(2.f * x) + 1.f); }

__device__ __forceinline__ void st_dsmem_u64(uint32_t saddr, uint32_t rk, unsigned long long v) {
    uint32_t ra;
    asm volatile("mapa.shared::cluster.u32 %0, %1, %2;" : "=r"(ra) : "r"(saddr), "r"(rk));
    asm volatile("st.shared::cluster.u64 [%0], %1;" :: "r"(ra), "l"(v) : "memory");
}
__device__ __forceinline__ void cluster_arrive() {
    asm volatile("barrier.cluster.arrive.aligned;" ::: "memory");
}
__device__ __forceinline__ void cluster_wait() {
    asm volatile("barrier.cluster.wait.aligned;" ::: "memory");
}

__global__ __launch_bounds__(RTH, 1) void gru_rec(const float* __restrict__ h0,
                                                  const float* __restrict__ W_hh,
                                                  const float* __restrict__ b_hh,
                                                  float* __restrict__ hs,
                                                  float* __restrict__ hT) {
    __shared__ alignas(16) float sh_h[2][2 * HDIM];      // [buf][b][k]
    __shared__ alignas(16) float2 sh_hgA[NROW];          // kh=0 partials (b0,b1)
    __shared__ alignas(16) float2 sh_hgB[NROW];          // kh=1 partials (b0,b1)

    uint32_t rank; asm("mov.u32 %0, %%cluster_ctarank;" : "=r"(rank));
    const int tid = threadIdx.x;
    const int cb = (blockIdx.x >> 2) * 2;

    const int kh = tid >= NROW;
    const int r  = tid - kh * NROW;
    const int g  = r >> 6, il = r & 63;
    const int grow = g * HDIM + (int)rank * IDXC + il;

    unsigned long long wq[64];
    {
        const ulonglong2* wp = (const ulonglong2*)(W_hh + (size_t)grow * HDIM + kh * 128);
#pragma unroll
        for (int j = 0; j < 32; j++) { ulonglong2 u = wp[j]; wq[2*j] = u.x; wq[2*j+1] = u.y; }
    }
    float bhr = 0.f, bhz = 0.f, bhn = 0.f;
    if (tid < 128) {
        int gil = tid & 63, gi = (int)rank * IDXC + gil;
        bhr = b_hh[gi]; bhz = b_hh[HDIM + gi]; bhn = b_hh[2 * HDIM + gi];
    }
    for (int i = tid; i < 2 * HDIM; i += RTH) {
        int b = i >> 8, k = i & 255;
        sh_h[0][b * HDIM + k] = h0[(size_t)(cb + b) * HDIM + k];
    }
    __syncthreads();
    cluster_arrive();
    cluster_wait();

    const int gb = tid >> 6, ggil = tid & 63;
    const size_t xg_gate_base = ((size_t)(cb + gb) * TDIM) * G3
                              + (size_t)rank * IDXC + ggil;

    const uint32_t h_s = (uint32_t)__cvta_generic_to_shared(sh_h);

    for (int t = 0; t < TDIM; t++) {
        const int cur = t & 1;
        const float* hb = sh_h[cur];

        float xr = 0.f, xz = 0.f, xn = 0.f;
        if (tid < 128) {
            const float* xp = g_xg + xg_gate_base + (size_t)t * G3;
            xr = xp[0]; xz = xp[256]; xn = xp[512];
        }

        const ulonglong2* hpA = (const ulonglong2*)(hb + kh * 128);
        const ulonglong2* hpB = (const ulonglong2*)(hb + HDIM + kh * 128);
        unsigned long long a0a = 0ull, a0b = 0ull, a1a = 0ull, a1b = 0ull;
#pragma unroll
        for (int c = 0; c < 16; c++) {
            ulonglong2 vA = hpA[c];
            a0a = fma2(wq[2*c+0], vA.x, a0a); a0a = fma2(wq[2*c+1], vA.y, a0a);
            ulonglong2 vB = hpB[c];
            a1a = fma2(wq[2*c+0], vB.x, a1a); a1a = fma2(wq[2*c+1], vB.y, a1a);
            ulonglong2 vA2 = hpA[16 + c];
            a0b = fma2(wq[32+2*c+0], vA2.x, a0b); a0b = fma2(wq[32+2*c+1], vA2.y, a0b);
            ulonglong2 vB2 = hpB[16 + c];
            a1b = fma2(wq[32+2*c+0], vB2.x, a1b); a1b = fma2(wq[32+2*c+1], vB2.y, a1b);
        }
        float s0, s1, xl, xh2;
        unsigned long long t0 = fma2(pk2(1.f, 1.f), a0a, a0b);
        upk2(t0, xl, xh2); s0 = xl + xh2;
        unsigned long long t1 = fma2(pk2(1.f, 1.f), a1a, a1b);
        upk2(t1, xl, xh2); s1 = xl + xh2;
        if (kh) sh_hgB[r] = make_float2(s0, s1);
        else    sh_hgA[r] = make_float2(s0, s1);
        __syncthreads();

        float hnew = 0.f, hpart = 0.f;
        int b = gb, gi = (int)rank * IDXC + ggil;
        if (tid < 128) {
            const int gil = ggil;
            float2 rA = sh_hgA[gil],        rB = sh_hgB[gil];
            float2 zA = sh_hgA[64 + gil],   zB = sh_hgB[64 + gil];
            float2 nA = sh_hgA[128 + gil],  nB = sh_hgB[128 + gil];
            float hr  = b ? (rA.y + rB.y) : (rA.x + rB.x);
            float hz  = b ? (zA.y + zB.y) : (zA.x + zB.x);
            float hnv = b ? (nA.y + nB.y) : (nA.x + nB.x);
            float hprev = hb[b * HDIM + gi];
            float rg = sigm_f(xr + hr + bhr);
            float zg = sigm_f(xz + hz + bhz);
            float ng = tanh_f(xn + rg * (hnv + bhn));
            hnew = (1.f - zg) * ng + zg * hprev;

            hpart = __shfl_down_sync(0xffffffffu, hnew, 1);
            if (t < TDIM - 1 && (ggil & 1) == 0) {
                unsigned long long pv = pk2(hnew, hpart);
                uint32_t laddr = h_s + 4u * (uint32_t)((cur ^ 1) * (2 * HDIM) + b * HDIM + gi);
#pragma unroll
                for (uint32_t dr = 0; dr < CLSZ; dr++) st_dsmem_u64(laddr, dr, pv);
            }
        }
        cluster_arrive();
        if (tid < 128) {
            if ((ggil & 1) == 0)
                *(float2*)&hs[((size_t)(cb + b) * TDIM + t) * HDIM + gi] = make_float2(hnew, hpart);
            if (t == TDIM - 1) hT[(size_t)(cb + b) * HDIM + gi] = hnew;
        }
        cluster_wait();
    }
}

// ---------------- launch ----------------
extern "C" void kernel_launch(void* const* d_in, const int* in_sizes, int n_in,
                              void* d_out, int out_size) {
    (void)in_sizes; (void)n_in; (void)out_size;
    const float* x    = (const float*)d_in[0];
    const float* h0   = (const float*)d_in[1];
    const float* W_ih = (const float*)d_in[2];
    const float* W_hh = (const float*)d_in[3];
    const float* b_ih = (const float*)d_in[4];
    const float* b_hh = (const float*)d_in[5];
    float* out = (float*)d_out;
    float* hs = out;
    float* hT = out + (size_t)BDIM * TDIM * HDIM;

    dim3 g1(G3 / BN, (BDIM * TDIM) / BM);   // N fast, M slow: x-tile L2 reuse
    proj_gemm<<<g1, 256>>>(x, W_ih, b_ih);

    cudaLaunchConfig_t cfg = {};
    cfg.gridDim = dim3(32 * CLSZ, 1, 1);
    cfg.blockDim = dim3(RTH, 1, 1);
    cfg.dynamicSmemBytes = 0;
    cfg.stream = 0;
    cudaLaunchAttribute attrs[1];
    attrs[0].id = cudaLaunchAttributeClusterDimension;
    attrs[0].val.clusterDim.x = CLSZ;
    attrs[0].val.clusterDim.y = 1;
    attrs[0].val.clusterDim.z = 1;
    cfg.attrs = attrs;
    cfg.numAttrs = 1;
    cudaLaunchKernelEx(&cfg, gru_rec, h0, W_hh, b_hh, hs, hT);
}

// round 11
// speedup vs baseline: 1.8426x; 1.0011x over previous
#include <cuda_runtime.h>
#include <cstdint>

#define BDIM 64
#define TDIM 2048
#define DDIM 256
#define HDIM 256
#define G3   768

__device__ float g_xg[(size_t)BDIM * TDIM * G3];

// ---------------- f32x2 helpers ----------------
__device__ __forceinline__ unsigned long long pk2(float x, float y) {
    unsigned long long r;
    asm("mov.b64 %0, {%1, %2};" : "=l"(r) : "f"(x), "f"(y));
    return r;
}
__device__ __forceinline__ void upk2(unsigned long long p, float& x, float& y) {
    asm("mov.b64 {%0, %1}, %2;" : "=f"(x), "=f"(y) : "l"(p));
}
__device__ __forceinline__ unsigned long long fma2(unsigned long long a,
                                                   unsigned long long b,
                                                   unsigned long long c) {
    unsigned long long d;
    asm("fma.rn.f32x2 %0, %1, %2, %3;" : "=l"(d) : "l"(a), "l"(b), "l"(c));
    return d;
}

// ---------------- Kernel 1: projection GEMM (dup-A smem, reg prefetch) ----------------
#define BM 64
#define BN 64
#define BK 32
#define AST (2 * BM + 8)   // duplicated-A row stride (floats), even for LDS.64 align
#define BST (BN + 8)

__global__ __launch_bounds__(256) void proj_gemm(const float* __restrict__ x,
                                                 const float* __restrict__ W,
                                                 const float* __restrict__ bias) {
    __shared__ float As2[BK][AST];   // A duplicated: [k][2m] == [k][2m+1]
    __shared__ float Bs[BK][BST];    // B: [k][n]
    const int tid = threadIdx.x;
    const int gn = blockIdx.x * BN;  // N fast dim: 12 adjacent blocks share x tile (L2)
    const int gm = blockIdx.y * BM;
    const int m4 = (tid >> 4) * 4;
    const int n4 = (tid & 15) * 4;

    // loader mapping: idx = tid + j*256 in [0,512): row = idx>>3, c4 = (idx&7)*4
    const int r0 = tid >> 3,        c40 = (tid & 7) * 4;
    const int r1 = (tid + 256) >> 3, c41 = c40;   // j=1: row = r0+32

    unsigned long long acc[4][2];
#pragma unroll
    for (int i = 0; i < 4; i++) { acc[i][0] = 0ull; acc[i][1] = 0ull; }

    // prologue: load tile 0
    float4 va0 = *(const float4*)&x[(size_t)(gm + r0) * DDIM + c40];
    float4 va1 = *(const float4*)&x[(size_t)(gm + r1) * DDIM + c41];
    float4 vb0 = *(const float4*)&W[(size_t)(gn + r0) * DDIM + c40];
    float4 vb1 = *(const float4*)&W[(size_t)(gn + r1) * DDIM + c41];
#pragma unroll
    for (int i = 0; i < 4; i++) {
        float v;
        v = (&va0.x)[i]; *(float2*)&As2[c40 + i][2 * r0] = make_float2(v, v);
        v = (&va1.x)[i]; *(float2*)&As2[c41 + i][2 * r1] = make_float2(v, v);
        Bs[c40 + i][r0] = (&vb0.x)[i];
        Bs[c41 + i][r1] = (&vb1.x)[i];
    }
    __syncthreads();

    for (int kt = 0; kt < DDIM / BK; kt++) {
        float4 na0, na1, nb0, nb1;
        if (kt < DDIM / BK - 1) {
            int ko = (kt + 1) * BK;
            na0 = *(const float4*)&x[(size_t)(gm + r0) * DDIM + ko + c40];
            na1 = *(const float4*)&x[(size_t)(gm + r1) * DDIM + ko + c41];
            nb0 = *(const float4*)&W[(size_t)(gn + r0) * DDIM + ko + c40];
            nb1 = *(const float4*)&W[(size_t)(gn + r1) * DDIM + ko + c41];
        }
#pragma unroll
        for (int k = 0; k < BK; k++) {
            ulonglong2 bp = *(const ulonglong2*)&Bs[k][n4];
            unsigned long long aa0 = *(const unsigned long long*)&As2[k][2 * (m4 + 0)];
            unsigned long long aa1 = *(const unsigned long long*)&As2[k][2 * (m4 + 1)];
            unsigned long long aa2 = *(const unsigned long long*)&As2[k][2 * (m4 + 2)];
            unsigned long long aa3 = *(const unsigned long long*)&As2[k][2 * (m4 + 3)];
            acc[0][0] = fma2(aa0, bp.x, acc[0][0]); acc[0][1] = fma2(aa0, bp.y, acc[0][1]);
            acc[1][0] = fma2(aa1, bp.x, acc[1][0]); acc[1][1] = fma2(aa1, bp.y, acc[1][1]);
            acc[2][0] = fma2(aa2, bp.x, acc[2][0]); acc[2][1] = fma2(aa2, bp.y, acc[2][1]);
            acc[3][0] = fma2(aa3, bp.x, acc[3][0]); acc[3][1] = fma2(aa3, bp.y, acc[3][1]);
        }
        __syncthreads();
        if (kt < DDIM / BK - 1) {
#pragma unroll
            for (int i = 0; i < 4; i++) {
                float v;
                v = (&na0.x)[i]; *(float2*)&As2[c40 + i][2 * r0] = make_float2(v, v);
                v = (&na1.x)[i]; *(float2*)&As2[c41 + i][2 * r1] = make_float2(v, v);
                Bs[c40 + i][r0] = (&nb0.x)[i];
                Bs[c41 + i][r1] = (&nb1.x)[i];
            }
            __syncthreads();
        }
    }

    float4 bb = *(const float4*)&bias[gn + n4];
#pragma unroll
    for (int mi = 0; mi < 4; mi++) {
        float o0, o1, o2, o3;
        upk2(acc[mi][0], o0, o1);
        upk2(acc[mi][1], o2, o3);
        float4 o = make_float4(o0 + bb.x, o1 + bb.y, o2 + bb.z, o3 + bb.w);
        *(float4*)&g_xg[(size_t)(gm + m4 + mi) * G3 + gn + n4] = o;
    }
}

// ---------------- Kernel 2: CLSZ=4, register W, cluster barrier (R7, verbatim) ----------------
#define CLSZ 4
#define RTH  384
#define IDXC 64
#define NROW 192

__device__ __forceinline__ float sigm_f(float x) { return 1.f / (1.f + __expf(-x)); }
__device__ __forceinline__ float tanh_f(float x) { return 1.f - 2.f / (__expf(2.f * x) + 1.f); }

__device__ __forceinline__ void st_dsmem_u64(uint32_t saddr, uint32_t rk, unsigned long long v) {
    uint32_t ra;
    asm volatile("mapa.shared::cluster.u32 %0, %1, %2;" : "=r"(ra) : "r"(saddr), "r"(rk));
    asm volatile("st.shared::cluster.u64 [%0], %1;" :: "r"(ra), "l"(v) : "memory");
}
__device__ __forceinline__ void cluster_arrive() {
    asm volatile("barrier.cluster.arrive.aligned;" ::: "memory");
}
__device__ __forceinline__ void cluster_wait() {
    asm volatile("barrier.cluster.wait.aligned;" ::: "memory");
}

__global__ __launch_bounds__(RTH, 1) void gru_rec(const float* __restrict__ h0,
                                                  const float* __restrict__ W_hh,
                                                  const float* __restrict__ b_hh,
                                                  float* __restrict__ hs,
                                                  float* __restrict__ hT) {
    __shared__ alignas(16) float sh_h[2][2 * HDIM];      // [buf][b][k]
    __shared__ alignas(16) float2 sh_hgA[NROW];          // kh=0 partials (b0,b1)
    __shared__ alignas(16) float2 sh_hgB[NROW];          // kh=1 partials (b0,b1)

    uint32_t rank; asm("mov.u32 %0, %%cluster_ctarank;" : "=r"(rank));
    const int tid = threadIdx.x;
    const int cb = (blockIdx.x >> 2) * 2;

    const int kh = tid >= NROW;
    const int r  = tid - kh * NROW;
    const int g  = r >> 6, il = r & 63;
    const int grow = g * HDIM + (int)rank * IDXC + il;

    unsigned long long wq[64];
    {
        const ulonglong2* wp = (const ulonglong2*)(W_hh + (size_t)grow * HDIM + kh * 128);
#pragma unroll
        for (int j = 0; j < 32; j++) { ulonglong2 u = wp[j]; wq[2*j] = u.x; wq[2*j+1] = u.y; }
    }
    float bhr = 0.f, bhz = 0.f, bhn = 0.f;
    if (tid < 128) {
        int gil = tid & 63, gi = (int)rank * IDXC + gil;
        bhr = b_hh[gi]; bhz = b_hh[HDIM + gi]; bhn = b_hh[2 * HDIM + gi];
    }
    for (int i = tid; i < 2 * HDIM; i += RTH) {
        int b = i >> 8, k = i & 255;
        sh_h[0][b * HDIM + k] = h0[(size_t)(cb + b) * HDIM + k];
    }
    __syncthreads();
    cluster_arrive();
    cluster_wait();

    const int gb = tid >> 6, ggil = tid & 63;
    const size_t xg_gate_base = ((size_t)(cb + gb) * TDIM) * G3
                              + (size_t)rank * IDXC + ggil;

    const uint32_t h_s = (uint32_t)__cvta_generic_to_shared(sh_h);

    for (int t = 0; t < TDIM; t++) {
        const int cur = t & 1;
        const float* hb = sh_h[cur];

        float xr = 0.f, xz = 0.f, xn = 0.f;
        if (tid < 128) {
            const float* xp = g_xg + xg_gate_base + (size_t)t * G3;
            xr = xp[0]; xz = xp[256]; xn = xp[512];
        }

        const ulonglong2* hpA = (const ulonglong2*)(hb + kh * 128);
        const ulonglong2* hpB = (const ulonglong2*)(hb + HDIM + kh * 128);
        unsigned long long a0a = 0ull, a0b = 0ull, a1a = 0ull, a1b = 0ull;
#pragma unroll
        for (int c = 0; c < 16; c++) {
            ulonglong2 vA = hpA[c];
            a0a = fma2(wq[2*c+0], vA.x, a0a); a0a = fma2(wq[2*c+1], vA.y, a0a);
            ulonglong2 vB = hpB[c];
            a1a = fma2(wq[2*c+0], vB.x, a1a); a1a = fma2(wq[2*c+1], vB.y, a1a);
            ulonglong2 vA2 = hpA[16 + c];
            a0b = fma2(wq[32+2*c+0], vA2.x, a0b); a0b = fma2(wq[32+2*c+1], vA2.y, a0b);
            ulonglong2 vB2 = hpB[16 + c];
            a1b = fma2(wq[32+2*c+0], vB2.x, a1b); a1b = fma2(wq[32+2*c+1], vB2.y, a1b);
        }
        float s0, s1, xl, xh2;
        unsigned long long t0 = fma2(pk2(1.f, 1.f), a0a, a0b);
        upk2(t0, xl, xh2); s0 = xl + xh2;
        unsigned long long t1 = fma2(pk2(1.f, 1.f), a1a, a1b);
        upk2(t1, xl, xh2); s1 = xl + xh2;
        if (kh) sh_hgB[r] = make_float2(s0, s1);
        else    sh_hgA[r] = make_float2(s0, s1);
        __syncthreads();

        float hnew = 0.f, hpart = 0.f;
        int b = gb, gi = (int)rank * IDXC + ggil;
        if (tid < 128) {
            const int gil = ggil;
            float2 rA = sh_hgA[gil],        rB = sh_hgB[gil];
            float2 zA = sh_hgA[64 + gil],   zB = sh_hgB[64 + gil];
            float2 nA = sh_hgA[128 + gil],  nB = sh_hgB[128 + gil];
            float hr  = b ? (rA.y + rB.y) : (rA.x + rB.x);
            float hz  = b ? (zA.y + zB.y) : (zA.x + zB.x);
            float hnv = b ? (nA.y + nB.y) : (nA.x + nB.x);
            float hprev = hb[b * HDIM + gi];
            float rg = sigm_f(xr + hr + bhr);
            float zg = sigm_f(xz + hz + bhz);
            float ng = tanh_f(xn + rg * (hnv + bhn));
            hnew = (1.f - zg) * ng + zg * hprev;

            hpart = __shfl_down_sync(0xffffffffu, hnew, 1);
            if (t < TDIM - 1 && (ggil & 1) == 0) {
                unsigned long long pv = pk2(hnew, hpart);
                uint32_t laddr = h_s + 4u * (uint32_t)((cur ^ 1) * (2 * HDIM) + b * HDIM + gi);
#pragma unroll
                for (uint32_t dr = 0; dr < CLSZ; dr++) st_dsmem_u64(laddr, dr, pv);
            }
        }
        cluster_arrive();
        if (tid < 128) {
            if ((ggil & 1) == 0)
                *(float2*)&hs[((size_t)(cb + b) * TDIM + t) * HDIM + gi] = make_float2(hnew, hpart);
            if (t == TDIM - 1) hT[(size_t)(cb + b) * HDIM + gi] = hnew;
        }
        cluster_wait();
    }
}

// ---------------- launch ----------------
extern "C" void kernel_launch(void* const* d_in, const int* in_sizes, int n_in,
                              void* d_out, int out_size) {
    (void)in_sizes; (void)n_in; (void)out_size;
    const float* x    = (const float*)d_in[0];
    const float* h0   = (const float*)d_in[1];
    const float* W_ih = (const float*)d_in[2];
    const float* W_hh = (const float*)d_in[3];
    const float* b_ih = (const float*)d_in[4];
    const float* b_hh = (const float*)d_in[5];
    float* out = (float*)d_out;
    float* hs = out;
    float* hT = out + (size_t)BDIM * TDIM * HDIM;

    dim3 g1(G3 / BN, (BDIM * TDIM) / BM);   // N fast, M slow: x-tile L2 reuse
    proj_gemm<<<g1, 256>>>(x, W_ih, b_ih);

    cudaLaunchConfig_t cfg = {};
    cfg.gridDim = dim3(32 * CLSZ, 1, 1);
    cfg.blockDim = dim3(RTH, 1, 1);
    cfg.dynamicSmemBytes = 0;
    cfg.stream = 0;
    cudaLaunchAttribute attrs[1];
    attrs[0].id = cudaLaunchAttributeClusterDimension;
    attrs[0].val.clusterDim.x = CLSZ;
    attrs[0].val.clusterDim.y = 1;
    attrs[0].val.clusterDim.z = 1;
    cfg.attrs = attrs;
    cfg.numAttrs = 1;
    cudaLaunchKernelEx(&cfg, gru_rec, h0, W_hh, b_hh, hs, hT);
}

// round 13
// speedup vs baseline: 2.4554x; 1.3326x over previous
#include <cuda_runtime.h>
#include <cuda_bf16.h>
#include <mma.h>
#include <cstdint>

using namespace nvcuda;

#define BDIM 64
#define TDIM 2048
#define DDIM 256
#define HDIM 256
#define G3   768
#define MTOT (BDIM * TDIM)

__device__ float g_xg[(size_t)MTOT * G3];
__device__ __nv_bfloat16 g_xh[(size_t)MTOT * DDIM];
__device__ __nv_bfloat16 g_xl[(size_t)MTOT * DDIM];
__device__ __nv_bfloat16 g_wh[(size_t)G3 * DDIM];
__device__ __nv_bfloat16 g_wl[(size_t)G3 * DDIM];

// ---------------- f32x2 helpers ----------------
__device__ __forceinline__ unsigned long long pk2(float x, float y) {
    unsigned long long r;
    asm("mov.b64 %0, {%1, %2};" : "=l"(r) : "f"(x), "f"(y));
    return r;
}
__device__ __forceinline__ void upk2(unsigned long long p, float& x, float& y) {
    asm("mov.b64 {%0, %1}, %2;" : "=f"(x), "=f"(y) : "l"(p));
}
__device__ __forceinline__ unsigned long long fma2(unsigned long long a,
                                                   unsigned long long b,
                                                   unsigned long long c) {
    unsigned long long d;
    asm("fma.rn.f32x2 %0, %1, %2, %3;" : "=l"(d) : "l"(a), "l"(b), "l"(c));
    return d;
}

// ---------------- Kernel 0: fp32 -> bf16 hi/lo split ----------------
__global__ __launch_bounds__(256) void split_bf16(const float4* __restrict__ src,
                                                  __nv_bfloat162* __restrict__ dh,
                                                  __nv_bfloat162* __restrict__ dl,
                                                  int n4) {
    int i = blockIdx.x * 256 + threadIdx.x;
    if (i >= n4) return;
    float4 v = src[i];
    __nv_bfloat16 h0 = __float2bfloat16(v.x), h1 = __float2bfloat16(v.y);
    __nv_bfloat16 h2 = __float2bfloat16(v.z), h3 = __float2bfloat16(v.w);
    __nv_bfloat16 l0 = __float2bfloat16(v.x - __bfloat162float(h0));
    __nv_bfloat16 l1 = __float2bfloat16(v.y - __bfloat162float(h1));
    __nv_bfloat16 l2 = __float2bfloat16(v.z - __bfloat162float(h2));
    __nv_bfloat16 l3 = __float2bfloat16(v.w - __bfloat162float(h3));
    __nv_bfloat162 a; a.x = h0; a.y = h1;
    __nv_bfloat162 b; b.x = h2; b.y = h3;
    dh[2 * i] = a; dh[2 * i + 1] = b;
    a.x = l0; a.y = l1; b.x = l2; b.y = l3;
    dl[2 * i] = a; dl[2 * i + 1] = b;
}

// ---------------- Kernel 1: wmma bf16 split-GEMM projection ----------------
// D[M=131072, N=768] = Ah*Bh^T + Ah*Bl^T + Al*Bh^T + bias
// tile 64x64, BK=32, 256 threads (8 warps as 2m x 4n)
#define PBM 64
#define PBN 64
#define PBK 32
#define AS  40    // A smem row stride (bf16), mult of 8
#define BS  40    // B smem row stride
#define CS  68    // C smem row stride (float), mult of 4

__global__ __launch_bounds__(256) void proj_wmma(const float* __restrict__ bias) {
    __shared__ __nv_bfloat16 As_h[PBM * AS], As_l[PBM * AS];
    __shared__ __nv_bfloat16 Bs_h[PBN * BS], Bs_l[PBN * BS];
    __shared__ float Cs[PBM * CS];

    const int tid = threadIdx.x, wid = tid >> 5;
    const int gn = blockIdx.x * PBN;    // n fast: 12 CTAs share A rows via L2
    const int gm = blockIdx.y * PBM;
    const int wm = wid & 1, wn = wid >> 1;

    // loader: each thread 1 uint4 (8 bf16) per matrix per tile
    const int lrow = tid >> 2, lk8 = (tid & 3) * 8;

    wmma::fragment<wmma::accumulator, 16, 16, 16, float> c0, c1;
    wmma::fill_fragment(c0, 0.f);
    wmma::fill_fragment(c1, 0.f);

    for (int kt = 0; kt < DDIM / PBK; kt++) {
        const int ko = kt * PBK + lk8;
        *(uint4*)&As_h[lrow * AS + lk8] = *(const uint4*)(g_xh + (size_t)(gm + lrow) * DDIM + ko);
        *(uint4*)&As_l[lrow * AS + lk8] = *(const uint4*)(g_xl + (size_t)(gm + lrow) * DDIM + ko);
        *(uint4*)&Bs_h[lrow * BS + lk8] = *(const uint4*)(g_wh + (size_t)(gn + lrow) * DDIM + ko);
        *(uint4*)&Bs_l[lrow * BS + lk8] = *(const uint4*)(g_wl + (size_t)(gn + lrow) * DDIM + ko);
        __syncthreads();

#pragma unroll
        for (int kk = 0; kk < PBK; kk += 16) {
            wmma::fragment<wmma::matrix_a, 16, 16, 16, __nv_bfloat16, wmma::row_major> ah0, ah1, al0, al1;
            wmma::fragment<wmma::matrix_b, 16, 16, 16, __nv_bfloat16, wmma::col_major> bh, bl;
            wmma::load_matrix_sync(ah0, &As_h[(wm * 32 + 0)  * AS + kk], AS);
            wmma::load_matrix_sync(ah1, &As_h[(wm * 32 + 16) * AS + kk], AS);
            wmma::load_matrix_sync(al0, &As_l[(wm * 32 + 0)  * AS + kk], AS);
            wmma::load_matrix_sync(al1, &As_l[(wm * 32 + 16) * AS + kk], AS);
            wmma::load_matrix_sync(bh, &Bs_h[(wn * 16) * BS + kk], BS);
            wmma::load_matrix_sync(bl, &Bs_l[(wn * 16) * BS + kk], BS);
            wmma::mma_sync(c0, ah0, bh, c0);
            wmma::mma_sync(c1, ah1, bh, c1);
            wmma::mma_sync(c0, ah0, bl, c0);
            wmma::mma_sync(c1, ah1, bl, c1);
            wmma::mma_sync(c0, al0, bh, c0);
            wmma::mma_sync(c1, al1, bh, c1);
        }
        __syncthreads();
    }

    // epilogue: frags -> smem -> (+bias) -> gmem
    wmma::store_matrix_sync(&Cs[(wm * 32 + 0)  * CS + wn * 16], c0, CS, wmma::mem_row_major);
    wmma::store_matrix_sync(&Cs[(wm * 32 + 16) * CS + wn * 16], c1, CS, wmma::mem_row_major);
    __syncthreads();

    const int erow = tid >> 2, ec16 = (tid & 3) * 16;
#pragma unroll
    for (int j = 0; j < 16; j += 4) {
        float4 bb = *(const float4*)&bias[gn + ec16 + j];
        float4 v = *(const float4*)&Cs[erow * CS + ec16 + j];
        v.x += bb.x; v.y += bb.y; v.z += bb.z; v.w += bb.w;
        *(float4*)&g_xg[(size_t)(gm + erow) * G3 + gn + ec16 + j] = v;
    }
}

// ---------------- Kernel 2: CLSZ=4, register W, cluster barrier (R7/R11, verbatim) ----------------
#define CLSZ 4
#define RTH  384
#define IDXC 64
#define NROW 192

__device__ __forceinline__ float sigm_f(float x) { return 1.f / (1.f + __expf(-x)); }
__device__ __forceinline__ float tanh_f(float x) { return 1.f - 2.f / (__expf(2.f * x) + 1.f); }

__device__ __forceinline__ void st_dsmem_u64(uint32_t saddr, uint32_t rk, unsigned long long v) {
    uint32_t ra;
    asm volatile("mapa.shared::cluster.u32 %0, %1, %2;" : "=r"(ra) : "r"(saddr), "r"(rk));
    asm volatile("st.shared::cluster.u64 [%0], %1;" :: "r"(ra), "l"(v) : "memory");
}
__device__ __forceinline__ void cluster_arrive() {
    asm volatile("barrier.cluster.arrive.aligned;" ::: "memory");
}
__device__ __forceinline__ void cluster_wait() {
    asm volatile("barrier.cluster.wait.aligned;" ::: "memory");
}

__global__ __launch_bounds__(RTH, 1) void gru_rec(const float* __restrict__ h0,
                                                  const float* __restrict__ W_hh,
                                                  const float* __restrict__ b_hh,
                                                  float* __restrict__ hs,
                                                  float* __restrict__ hT) {
    __shared__ alignas(16) float sh_h[2][2 * HDIM];
    __shared__ alignas(16) float2 sh_hgA[NROW];
    __shared__ alignas(16) float2 sh_hgB[NROW];

    uint32_t rank; asm("mov.u32 %0, %%cluster_ctarank;" : "=r"(rank));
    const int tid = threadIdx.x;
    const int cb = (blockIdx.x >> 2) * 2;

    const int kh = tid >= NROW;
    const int r  = tid - kh * NROW;
    const int g  = r >> 6, il = r & 63;
    const int grow = g * HDIM + (int)rank * IDXC + il;

    unsigned long long wq[64];
    {
        const ulonglong2* wp = (const ulonglong2*)(W_hh + (size_t)grow * HDIM + kh * 128);
#pragma unroll
        for (int j = 0; j < 32; j++) { ulonglong2 u = wp[j]; wq[2*j] = u.x; wq[2*j+1] = u.y; }
    }
    float bhr = 0.f, bhz = 0.f, bhn = 0.f;
    if (tid < 128) {
        int gil = tid & 63, gi = (int)rank * IDXC + gil;
        bhr = b_hh[gi]; bhz = b_hh[HDIM + gi]; bhn = b_hh[2 * HDIM + gi];
    }
    for (int i = tid; i < 2 * HDIM; i += RTH) {
        int b = i >> 8, k = i & 255;
        sh_h[0][b * HDIM + k] = h0[(size_t)(cb + b) * HDIM + k];
    }
    __syncthreads();
    cluster_arrive();
    cluster_wait();

    const int gb = tid >> 6, ggil = tid & 63;
    const size_t xg_gate_base = ((size_t)(cb + gb) * TDIM) * G3
                              + (size_t)rank * IDXC + ggil;

    const uint32_t h_s = (uint32_t)__cvta_generic_to_shared(sh_h);

    for (int t = 0; t < TDIM; t++) {
        const int cur = t & 1;
        const float* hb = sh_h[cur];

        float xr = 0.f, xz = 0.f, xn = 0.f;
        if (tid < 128) {
            const float* xp = g_xg + xg_gate_base + (size_t)t * G3;
            xr = xp[0]; xz = xp[256]; xn = xp[512];
        }

        const ulonglong2* hpA = (const ulonglong2*)(hb + kh * 128);
        const ulonglong2* hpB = (const ulonglong2*)(hb + HDIM + kh * 128);
        unsigned long long a0a = 0ull, a0b = 0ull, a1a = 0ull, a1b = 0ull;
#pragma unroll
        for (int c = 0; c < 16; c++) {
            ulonglong2 vA = hpA[c];
            a0a = fma2(wq[2*c+0], vA.x, a0a); a0a = fma2(wq[2*c+1], vA.y, a0a);
            ulonglong2 vB = hpB[c];
            a1a = fma2(wq[2*c+0], vB.x, a1a); a1a = fma2(wq[2*c+1], vB.y, a1a);
            ulonglong2 vA2 = hpA[16 + c];
            a0b = fma2(wq[32+2*c+0], vA2.x, a0b); a0b = fma2(wq[32+2*c+1], vA2.y, a0b);
            ulonglong2 vB2 = hpB[16 + c];
            a1b = fma2(wq[32+2*c+0], vB2.x, a1b); a1b = fma2(wq[32+2*c+1], vB2.y, a1b);
        }
        float s0, s1, xl, xh2;
        unsigned long long t0 = fma2(pk2(1.f, 1.f), a0a, a0b);
        upk2(t0, xl, xh2); s0 = xl + xh2;
        unsigned long long t1 = fma2(pk2(1.f, 1.f), a1a, a1b);
        upk2(t1, xl, xh2); s1 = xl + xh2;
        if (kh) sh_hgB[r] = make_float2(s0, s1);
        else    sh_hgA[r] = make_float2(s0, s1);
        __syncthreads();

        float hnew = 0.f, hpart = 0.f;
        int b = gb, gi = (int)rank * IDXC + ggil;
        if (tid < 128) {
            const int gil = ggil;
            float2 rA = sh_hgA[gil],        rB = sh_hgB[gil];
            float2 zA = sh_hgA[64 + gil],   zB = sh_hgB[64 + gil];
            float2 nA = sh_hgA[128 + gil],  nB = sh_hgB[128 + gil];
            float hr  = b ? (rA.y + rB.y) : (rA.x + rB.x);
            float hz  = b ? (zA.y + zB.y) : (zA.x + zB.x);
            float hnv = b ? (nA.y + nB.y) : (nA.x + nB.x);
            float hprev = hb[b * HDIM + gi];
            float rg = sigm_f(xr + hr + bhr);
            float zg = sigm_f(xz + hz + bhz);
            float ng = tanh_f(xn + rg * (hnv + bhn));
            hnew = (1.f - zg) * ng + zg * hprev;

            hpart = __shfl_down_sync(0xffffffffu, hnew, 1);
            if (t < TDIM - 1 && (ggil & 1) == 0) {
                unsigned long long pv = pk2(hnew, hpart);
                uint32_t laddr = h_s + 4u * (uint32_t)((cur ^ 1) * (2 * HDIM) + b * HDIM + gi);
#pragma unroll
                for (uint32_t dr = 0; dr < CLSZ; dr++) st_dsmem_u64(laddr, dr, pv);
            }
        }
        cluster_arrive();
        if (tid < 128) {
            if ((ggil & 1) == 0)
                *(float2*)&hs[((size_t)(cb + b) * TDIM + t) * HDIM + gi] = make_float2(hnew, hpart);
            if (t == TDIM - 1) hT[(size_t)(cb + b) * HDIM + gi] = hnew;
        }
        cluster_wait();
    }
}

// ---------------- launch ----------------
extern "C" void kernel_launch(void* const* d_in, const int* in_sizes, int n_in,
                              void* d_out, int out_size) {
    (void)in_sizes; (void)n_in; (void)out_size;
    const float* x    = (const float*)d_in[0];
    const float* h0   = (const float*)d_in[1];
    const float* W_ih = (const float*)d_in[2];
    const float* W_hh = (const float*)d_in[3];
    const float* b_ih = (const float*)d_in[4];
    const float* b_hh = (const float*)d_in[5];
    float* out = (float*)d_out;
    float* hs = out;
    float* hT = out + (size_t)MTOT * HDIM;

    void *p_xh, *p_xl, *p_wh, *p_wl;
    cudaGetSymbolAddress(&p_xh, g_xh);
    cudaGetSymbolAddress(&p_xl, g_xl);
    cudaGetSymbolAddress(&p_wh, g_wh);
    cudaGetSymbolAddress(&p_wl, g_wl);

    // split x and W_ih into bf16 hi/lo
    {
        int n4x = (MTOT * DDIM) / 4;
        split_bf16<<<(n4x + 255) / 256, 256>>>((const float4*)x,
                                               (__nv_bfloat162*)p_xh, (__nv_bfloat162*)p_xl, n4x);
        int n4w = (G3 * DDIM) / 4;
        split_bf16<<<(n4w + 255) / 256, 256>>>((const float4*)W_ih,
                                               (__nv_bfloat162*)p_wh, (__nv_bfloat162*)p_wl, n4w);
    }

    // tensor-core projection (wmma bf16, 3-pass split)
    dim3 gp(G3 / PBN, MTOT / PBM);
    proj_wmma<<<gp, 256>>>(b_ih);

    // recurrence
    cudaLaunchConfig_t cfg = {};
    cfg.gridDim = dim3(32 * CLSZ, 1, 1);
    cfg.blockDim = dim3(RTH, 1, 1);
    cfg.dynamicSmemBytes = 0;
    cfg.stream = 0;
    cudaLaunchAttribute attrs[1];
    attrs[0].id = cudaLaunchAttributeClusterDimension;
    attrs[0].val.clusterDim.x = CLSZ;
    attrs[0].val.clusterDim.y = 1;
    attrs[0].val.clusterDim.z = 1;
    cfg.attrs = attrs;
    cfg.numAttrs = 1;
    cudaLaunchKernelEx(&cfg, gru_rec, h0, W_hh, b_hh, hs, hT);
}